// round 9
// baseline (speedup 1.0000x reference)
#include <cuda_runtime.h>

#define MAX_BLOCKS 2048

// Scratch (device allocation is forbidden in kernel_launch)
__device__ float g_blocksum[MAX_BLOCKS];
__device__ unsigned int g_done = 0;

// Per-row product term with early termination; returns (1 - prod) on lane 0.
// Factors are in (0,1] so the running product is non-increasing; stopping
// below EPS adds < EPS absolute error per row (loss is O(1e3)).
__device__ __forceinline__ float row_term(
    const float* __restrict__ xrow,
    const longlong2* __restrict__ yrow2,
    int L, int lane, float a0, float c0)
{
    const float EPS = 1e-12f;
    const int npairs = L >> 1;

    float acc = (lane < npairs) ? (1.0f - a0) * (1.0f - c0) : 1.0f;
    #pragma unroll
    for (int off = 16; off > 0; off >>= 1)
        acc *= __shfl_xor_sync(0xffffffffu, acc, off);
    float total = acc;

    // Rare continuation (~3e-6 of rows): need > 64 elements before underflow.
    for (int pbase = 32; pbase < npairs && total >= EPS; pbase += 32) {
        const int p = pbase + lane;
        float f = 1.0f;
        if (p < npairs) {
            longlong2 v = __ldg(yrow2 + p);
            f = (1.0f - __ldg(xrow + (int)v.x))
              * (1.0f - __ldg(xrow + (int)v.y));
        }
        #pragma unroll
        for (int off = 16; off > 0; off >>= 1)
            f *= __shfl_xor_sync(0xffffffffu, f, off);
        total *= f;
    }

    // Odd tail (j = L-1): element L is in-row since L <= maxL-1.
    if (lane == 0) {
        if ((L & 1) && total >= EPS) {
            longlong2 v = __ldg(yrow2 + npairs);
            total *= (1.0f - __ldg(xrow + (int)v.x));
        }
        return 1.0f - total;
    }
    return 0.0f;
}

// 16 warps per block, TWO rows per warp (independent chains -> MLP overlap).
__global__ __launch_bounds__(512) void fused_loss_kernel(
    const float* __restrict__ x,
    const long long* __restrict__ y,
    const long long* __restrict__ lengths,
    float* __restrict__ out,
    int maxL, int C, int B)
{
    const int tid  = threadIdx.x;
    const int lane = tid & 31;
    const int wid  = tid >> 5;
    const int bA   = blockIdx.x * 32 + wid * 2;
    const int bB   = bA + 1;

    __shared__ float swarp[16];

    float term = 0.0f;

    // ---- Issue both rows' chunk-0 y loads immediately (unconditional on L:
    // all maxL entries are valid indices), then lengths, then both gathers.
    // Two independent DRAM chains overlap within the warp.
    const bool haveA = (bA < B);
    const bool haveB = (bB < B);

    const float* __restrict__ xrowA = x + (size_t)bA * C;
    const float* __restrict__ xrowB = x + (size_t)bB * C;
    const longlong2* __restrict__ yrow2A = (const longlong2*)(y + (size_t)bA * maxL);
    const longlong2* __restrict__ yrow2B = (const longlong2*)(y + (size_t)bB * maxL);

    longlong2 vA = make_longlong2(0, 0), vB = make_longlong2(0, 0);
    const bool inrow = (2 * lane + 1) < maxL;
    if (haveA && inrow) vA = __ldg(yrow2A + lane);
    if (haveB && inrow) vB = __ldg(yrow2B + lane);

    const int LA = haveA ? (int)lengths[bA] : 0;
    const int LB = haveB ? (int)lengths[bB] : 0;

    float aA = 0.f, cA = 0.f, aB = 0.f, cB = 0.f;
    if (haveA) { aA = __ldg(xrowA + (int)vA.x); cA = __ldg(xrowA + (int)vA.y); }
    if (haveB) { aB = __ldg(xrowB + (int)vB.x); cB = __ldg(xrowB + (int)vB.y); }

    if (haveA) term += row_term(xrowA, yrow2A, LA, lane, aA, cA);
    if (haveB) term += row_term(xrowB, yrow2B, LB, lane, aB, cB);

    // Per-block partial sum (deterministic fixed order).
    if (lane == 0) swarp[wid] = term;
    __syncthreads();

    const unsigned int nblocks = (unsigned int)((B + 31) / 32);
    __shared__ unsigned int sdone;
    if (tid == 0) {
        float bs = 0.0f;
        #pragma unroll
        for (int w = 0; w < 16; w++) bs += swarp[w];
        g_blocksum[blockIdx.x] = bs;
        // acq_rel atomic: release publishes the STG above; the acquire on the
        // final increment makes all earlier blocks' sums visible. Replaces
        // __threadfence() (gpu-scope membar) + relaxed atomicAdd.
        unsigned int* p = &g_done;
        unsigned int old;
        asm volatile("atom.acq_rel.gpu.global.add.u32 %0, [%1], 1;"
                     : "=r"(old) : "l"(p) : "memory");
        sdone = old;
    }
    __syncthreads();

    if (sdone == nblocks - 1) {
        float s = (tid < (int)nblocks) ? g_blocksum[tid] : 0.0f;
        #pragma unroll
        for (int off = 16; off > 0; off >>= 1)
            s += __shfl_xor_sync(0xffffffffu, s, off);
        if (lane == 0) swarp[wid] = s;
        __syncthreads();
        if (tid == 0) {
            float t = 0.0f;
            #pragma unroll
            for (int w = 0; w < 16; w++) t += swarp[w];
            out[0] = t;
            g_done = 0;                 // reset for next graph replay
        }
    }
}

extern "C" void kernel_launch(void* const* d_in, const int* in_sizes, int n_in,
                              void* d_out, int out_size)
{
    const float*     x       = (const float*)d_in[0];
    const long long* y       = (const long long*)d_in[1];
    const long long* lengths = (const long long*)d_in[2];
    float* out = (float*)d_out;

    const int N    = in_sizes[2];       // lengths has N elements
    const int B    = N / 8;
    const int maxL = in_sizes[1] / N;   // y is N x MAXL
    const int C    = in_sizes[0] / N;   // x is N x C

    fused_loss_kernel<<<(B + 31) / 32, 512>>>(x, y, lengths, out, maxL, C, B);
}